// round 12
// baseline (speedup 1.0000x reference)
#include <cuda_runtime.h>
#include <cuda_bf16.h>
#include <cuda_fp16.h>
#include <cstdint>

#define S 4096
#define HH 64
#define WW 64

// ---------------- scratch (no allocations allowed) ----------------
__device__ float g_hqkv[4 * 96 * S];
__device__ float g_mkv [4 * 64 * S];
__device__ float g_Z2  [4 * 64 * S];
__device__ float g_Zp  [4 * 32 * S];
__device__ float g_conv[4 * 192 * S];
__device__ float g_hr  [4 * 64 * S];        // tf32-pre-rounded h
__device__ uint4 g_wfrag[36 * 1152];        // fragment-major conv weights

// ---------------- helpers ----------------
__device__ __forceinline__ uint32_t smem_u32(const void* p) {
    uint32_t a;
    asm("{ .reg .u64 t; cvta.to.shared.u64 t, %1; cvt.u32.u64 %0, t; }" : "=r"(a) : "l"(p));
    return a;
}
__device__ __forceinline__ void cpa4(uint32_t dst, const void* src, uint32_t sz) {
    asm volatile("cp.async.ca.shared.global [%0], [%1], 4, %2;" :: "r"(dst), "l"(src), "r"(sz));
}
__device__ __forceinline__ void cpa16(uint32_t dst, const void* src) {
    asm volatile("cp.async.cg.shared.global [%0], [%1], 16;" :: "r"(dst), "l"(src));
}
#define CP_COMMIT() asm volatile("cp.async.commit_group;" ::: "memory")
#define CP_WAIT0()  asm volatile("cp.async.wait_group 0;" ::: "memory")

__device__ __forceinline__ void mma16816(float* c, const uint32_t* a, uint32_t b0, uint32_t b1) {
    asm volatile(
        "mma.sync.aligned.m16n8k16.row.col.f32.bf16.bf16.f32 "
        "{%0,%1,%2,%3}, {%4,%5,%6,%7}, {%8,%9}, {%0,%1,%2,%3};"
        : "+f"(c[0]), "+f"(c[1]), "+f"(c[2]), "+f"(c[3])
        : "r"(a[0]), "r"(a[1]), "r"(a[2]), "r"(a[3]), "r"(b0), "r"(b1));
}
__device__ __forceinline__ void mma16816h(float* c, const uint32_t* a, uint32_t b0, uint32_t b1) {
    asm volatile(
        "mma.sync.aligned.m16n8k16.row.col.f32.f16.f16.f32 "
        "{%0,%1,%2,%3}, {%4,%5,%6,%7}, {%8,%9}, {%0,%1,%2,%3};"
        : "+f"(c[0]), "+f"(c[1]), "+f"(c[2]), "+f"(c[3])
        : "r"(a[0]), "r"(a[1]), "r"(a[2]), "r"(a[3]), "r"(b0), "r"(b1));
}
__device__ __forceinline__ void mma1688t(float* c, const uint32_t* a, uint32_t b0, uint32_t b1) {
    asm volatile(
        "mma.sync.aligned.m16n8k8.row.col.f32.tf32.tf32.f32 "
        "{%0,%1,%2,%3}, {%4,%5,%6,%7}, {%8,%9}, {%0,%1,%2,%3};"
        : "+f"(c[0]), "+f"(c[1]), "+f"(c[2]), "+f"(c[3])
        : "r"(a[0]), "r"(a[1]), "r"(a[2]), "r"(a[3]), "r"(b0), "r"(b1));
}
__device__ __forceinline__ uint32_t packbf(float lo, float hi) {
    uint32_t r;
    asm("cvt.rn.bf16x2.f32 %0, %2, %1;" : "=r"(r) : "f"(lo), "f"(hi));
    return r;
}
__device__ __forceinline__ uint32_t packh(float lo, float hi) {
    uint32_t r;
    asm("cvt.rn.f16x2.f32 %0, %2, %1;" : "=r"(r) : "f"(lo), "f"(hi));
    return r;
}
__device__ __forceinline__ uint32_t h2ex2(uint32_t x) {
    uint32_t r;
    asm("ex2.approx.f16x2 %0, %1;" : "=r"(r) : "r"(x));
    return r;
}
__device__ __forceinline__ uint32_t hadd2u(uint32_t a, uint32_t b) {
    uint32_t r;
    asm("add.rn.f16x2 %0, %1, %2;" : "=r"(r) : "r"(a), "r"(b));
    return r;
}
__device__ __forceinline__ uint32_t f2tf32(float f) {
    uint32_t r;
    asm("cvt.rna.tf32.f32 %0, %1;" : "=r"(r) : "f"(f));
    return r;
}

// ---------------- setup: conv weight pre-transform + h pre-round ----------------
__global__ __launch_bounds__(256)
void wpack_kernel(const float* __restrict__ Wo) {
    int b = blockIdx.x;               // 0..35: cog = b/6, cig = b%6
    int cog = b / 6, cig = b - cog * 6;
    for (int i = threadIdx.x; i < 1152; i += 256) {
        int ln = i & 31, mtc = i >> 5;
        int mt = mtc & 1, chunk = mtc >> 1;
        int khkw = chunk >> 1, c8 = chunk & 1;
        int ciL = c8 * 8 + (ln & 3);
        int co0 = mt * 16 + (ln >> 2);
        const float* wp = Wo + (((size_t)cog * 32 + co0) * 96 + cig * 16 + ciL) * 9 + khkw;
        g_wfrag[b * 1152 + i] = make_uint4(f2tf32(wp[0]), f2tf32(wp[8 * 864]),
                                           f2tf32(wp[36]), f2tf32(wp[8 * 864 + 36]));
    }
}

__global__ __launch_bounds__(256)
void roundh_kernel(const float* __restrict__ h, float* __restrict__ hr) {
    int i = blockIdx.x * 256 + threadIdx.x;     // over 262144 float4
    float4 v = ((const float4*)h)[i];
    v.x = __uint_as_float(f2tf32(v.x));
    v.y = __uint_as_float(f2tf32(v.y));
    v.z = __uint_as_float(f2tf32(v.z));
    v.w = __uint_as_float(f2tf32(v.w));
    ((float4*)hr)[i] = v;
}

// ---------------- merged 1x1 projection (h:96co / m:64co), X staged once ----------------
#define PRJ_XS_ST 136
#define PRJ_WS_ST 40

__global__ __launch_bounds__(128)
void projhm_kernel(const float* __restrict__ h, const float* __restrict__ Wh,
                   const float* __restrict__ bh, float* __restrict__ hqkv,
                   const float* __restrict__ m, const float* __restrict__ Wm,
                   const float* __restrict__ bm, float* __restrict__ mkv) {
    __shared__ uint32_t Xs[64 * PRJ_XS_ST];
    __shared__ uint32_t Ws2[64 * PRJ_WS_ST];
    int tid = threadIdx.x;
    int w = tid >> 5, lane = tid & 31;
    int lq = lane >> 2, l4 = lane & 3;
    int n = blockIdx.z, io = blockIdx.y;
    int s0 = blockIdx.x * 128;

    const float* Xg = (io == 0) ? h + (size_t)n * 64 * S : m + (size_t)n * 64 * S;
    const float* Wg = (io == 0) ? Wh : Wm;
    const float* bg = (io == 0) ? bh : bm;
    float* outg = (io == 0) ? g_hqkv + (size_t)n * 96 * S : g_mkv + (size_t)n * 64 * S;
    int ncg = (io == 0) ? 3 : 2;

    for (int i = tid; i < 64 * 128; i += 128) {
        int ci = i >> 7, sl = i & 127;
        Xs[ci * PRJ_XS_ST + sl] = f2tf32(Xg[(size_t)ci * S + s0 + sl]);
    }

    for (int cg = 0; cg < ncg; cg++) {
        for (int i = tid; i < 32 * 64; i += 128) {
            int co = i >> 6, ci = i & 63;
            Ws2[ci * PRJ_WS_ST + co] = f2tf32(Wg[(cg * 32 + co) * 64 + ci]);
        }
        __syncthreads();

        float oacc[2][4][4];
#pragma unroll
        for (int mt = 0; mt < 2; mt++)
#pragma unroll
            for (int nt = 0; nt < 4; nt++)
#pragma unroll
                for (int r = 0; r < 4; r++) oacc[mt][nt][r] = 0.f;

#pragma unroll
        for (int kb8 = 0; kb8 < 8; kb8++) {
            int kb = kb8 * 8;
            uint32_t a[2][4];
#pragma unroll
            for (int mt = 0; mt < 2; mt++) {
                int co0 = mt * 16 + lq;
                a[mt][0] = Ws2[(kb + l4) * PRJ_WS_ST + co0];
                a[mt][1] = Ws2[(kb + l4) * PRJ_WS_ST + co0 + 8];
                a[mt][2] = Ws2[(kb + l4 + 4) * PRJ_WS_ST + co0];
                a[mt][3] = Ws2[(kb + l4 + 4) * PRJ_WS_ST + co0 + 8];
            }
#pragma unroll
            for (int nt = 0; nt < 4; nt++) {
                int scol = w * 32 + nt * 8 + lq;
                uint32_t b0 = Xs[(kb + l4) * PRJ_XS_ST + scol];
                uint32_t b1 = Xs[(kb + l4 + 4) * PRJ_XS_ST + scol];
                mma1688t(oacc[0][nt], a[0], b0, b1);
                mma1688t(oacc[1][nt], a[1], b0, b1);
            }
        }

#pragma unroll
        for (int mt = 0; mt < 2; mt++) {
            int coA = cg * 32 + mt * 16 + lq, coB = coA + 8;
            float bA = bg[coA], bB = bg[coB];
#pragma unroll
            for (int nt = 0; nt < 4; nt++) {
                int x = s0 + w * 32 + nt * 8 + 2 * l4;
                *(float2*)&outg[(size_t)coA * S + x] = make_float2(oacc[mt][nt][0] + bA, oacc[mt][nt][1] + bA);
                *(float2*)&outg[(size_t)coB * S + x] = make_float2(oacc[mt][nt][2] + bB, oacc[mt][nt][3] + bB);
            }
        }
        __syncthreads();
    }
}

// projz: same GEMM, epilogue rounds output to tf32 (conv consumes it raw)
__global__ __launch_bounds__(128)
void projz_kernel(const float* __restrict__ Z2, const float* __restrict__ Wz,
                  const float* __restrict__ bz, float* __restrict__ Zp) {
    __shared__ uint32_t Xs[64 * PRJ_XS_ST];
    __shared__ uint32_t Ws2[64 * PRJ_WS_ST];
    int tid = threadIdx.x;
    int w = tid >> 5, lane = tid & 31;
    int lq = lane >> 2, l4 = lane & 3;
    int n = blockIdx.z;
    int s0 = blockIdx.x * 128;
    const float* Xg = Z2 + (size_t)n * 64 * S;
    float* outg = Zp + (size_t)n * 32 * S;

    for (int i = tid; i < 64 * 128; i += 128) {
        int ci = i >> 7, sl = i & 127;
        Xs[ci * PRJ_XS_ST + sl] = f2tf32(Xg[(size_t)ci * S + s0 + sl]);
    }
    for (int i = tid; i < 32 * 64; i += 128) {
        int co = i >> 6, ci = i & 63;
        Ws2[ci * PRJ_WS_ST + co] = f2tf32(Wz[co * 64 + ci]);
    }
    __syncthreads();

    float oacc[2][4][4];
#pragma unroll
    for (int mt = 0; mt < 2; mt++)
#pragma unroll
        for (int nt = 0; nt < 4; nt++)
#pragma unroll
            for (int r = 0; r < 4; r++) oacc[mt][nt][r] = 0.f;

#pragma unroll
    for (int kb8 = 0; kb8 < 8; kb8++) {
        int kb = kb8 * 8;
        uint32_t a[2][4];
#pragma unroll
        for (int mt = 0; mt < 2; mt++) {
            int co0 = mt * 16 + lq;
            a[mt][0] = Ws2[(kb + l4) * PRJ_WS_ST + co0];
            a[mt][1] = Ws2[(kb + l4) * PRJ_WS_ST + co0 + 8];
            a[mt][2] = Ws2[(kb + l4 + 4) * PRJ_WS_ST + co0];
            a[mt][3] = Ws2[(kb + l4 + 4) * PRJ_WS_ST + co0 + 8];
        }
#pragma unroll
        for (int nt = 0; nt < 4; nt++) {
            int scol = w * 32 + nt * 8 + lq;
            uint32_t b0 = Xs[(kb + l4) * PRJ_XS_ST + scol];
            uint32_t b1 = Xs[(kb + l4 + 4) * PRJ_XS_ST + scol];
            mma1688t(oacc[0][nt], a[0], b0, b1);
            mma1688t(oacc[1][nt], a[1], b0, b1);
        }
    }

#pragma unroll
    for (int mt = 0; mt < 2; mt++) {
        int coA = mt * 16 + lq, coB = coA + 8;
        float bA = bz[coA], bB = bz[coB];
#pragma unroll
        for (int nt = 0; nt < 4; nt++) {
            int x = s0 + w * 32 + nt * 8 + 2 * l4;
            *(float2*)&outg[(size_t)coA * S + x] =
                make_float2(__uint_as_float(f2tf32(oacc[mt][nt][0] + bA)),
                            __uint_as_float(f2tf32(oacc[mt][nt][1] + bA)));
            *(float2*)&outg[(size_t)coB * S + x] =
                make_float2(__uint_as_float(f2tf32(oacc[mt][nt][2] + bB)),
                            __uint_as_float(f2tf32(oacc[mt][nt][3] + bB)));
        }
    }
}

// ---------------- flash attention (round-10 version, unchanged) ----------------
#define AQ_W   2560
#define AK_W   1280
#define AV_W   1120
#define A_TOT  (AQ_W + 2 * AK_W + 2 * AV_W)

__global__ __launch_bounds__(128)
void attn_mma_kernel(const float* __restrict__ hqkv, const float* __restrict__ mkv,
                     float* __restrict__ Z2) {
    __shared__ uint32_t smw[A_TOT];
    uint32_t* Qsw = smw;
    uint32_t* Kb0 = smw + AQ_W;
    uint32_t* Vb0 = smw + AQ_W + 2 * AK_W;
    __nv_bfloat16* Qh = (__nv_bfloat16*)Qsw;

    int tid = threadIdx.x;
    int w = tid >> 5, lane = tid & 31;
    int lq = lane >> 2, lj = lane & 3;
    int n = blockIdx.z, att = blockIdx.y;
    int q0 = blockIdx.x * 128;

    const float* Q = hqkv + (size_t)n * 96 * S;
    const float* K = (att == 0) ? hqkv + ((size_t)n * 96 + 32) * S
                                : mkv  + ((size_t)n * 64 +  0) * S;
    const float* V = (att == 0) ? hqkv + ((size_t)n * 96 + 64) * S
                                : mkv  + ((size_t)n * 64 + 32) * S;
    float* Out = Z2 + ((size_t)n * 64 + att * 32) * S;

    const float scale = 0.17677669529663687f * 1.4426950408889634f;
    for (int i = tid; i < 4096; i += 128) {
        int d = i >> 7, q = i & 127;
        Qh[q * 40 + d] = __float2bfloat16(Q[(size_t)d * S + q0 + q] * scale);
    }
    __syncthreads();

    uint32_t qa[2][2][4];
#pragma unroll
    for (int mt = 0; mt < 2; mt++) {
        int r0 = 32 * w + 16 * mt + lq;
#pragma unroll
        for (int ks = 0; ks < 2; ks++) {
            qa[mt][ks][0] = Qsw[r0 * 20 + ks * 8 + lj];
            qa[mt][ks][1] = Qsw[(r0 + 8) * 20 + ks * 8 + lj];
            qa[mt][ks][2] = Qsw[r0 * 20 + ks * 8 + lj + 4];
            qa[mt][ks][3] = Qsw[(r0 + 8) * 20 + ks * 8 + lj + 4];
        }
    }

    float oacc[2][4][4];
#pragma unroll
    for (int mt = 0; mt < 2; mt++)
#pragma unroll
        for (int nt = 0; nt < 4; nt++)
#pragma unroll
            for (int r = 0; r < 4; r++) oacc[mt][nt][r] = 0.f;
    float l_acc[4] = {0.f, 0.f, 0.f, 0.f};

    uint32_t kreg[8], vreg[8];
#pragma unroll
    for (int j = 0; j < 8; j++) {
        int idx = j * 128 + tid;
        int k = idx & 63, dp = idx >> 6;
        kreg[j] = packbf(K[(size_t)(2 * dp) * S + k], K[(size_t)(2 * dp + 1) * S + k]);
    }
#pragma unroll
    for (int j = 0; j < 8; j++) {
        int idx = j * 128 + tid;
        int d = idx >> 5, kp = idx & 31;
        float2 v2 = *(const float2*)&V[(size_t)d * S + 2 * kp];
        vreg[j] = packh(v2.x, v2.y);
    }

#pragma unroll 1
    for (int kt = 0; kt < 64; kt++) {
        uint32_t* Kbuf = Kb0 + (kt & 1) * AK_W;
        uint32_t* Vbuf = Vb0 + (kt & 1) * AV_W;
#pragma unroll
        for (int j = 0; j < 8; j++) {
            int idx = j * 128 + tid;
            Kbuf[(idx & 63) * 20 + (idx >> 6)] = kreg[j];
        }
#pragma unroll
        for (int j = 0; j < 8; j++) {
            int idx = j * 128 + tid;
            Vbuf[(idx >> 5) * 35 + (idx & 31)] = vreg[j];
        }
        __syncthreads();

        if (kt < 63) {
            int kb = (kt + 1) * 64;
#pragma unroll
            for (int j = 0; j < 8; j++) {
                int idx = j * 128 + tid;
                int k = idx & 63, dp = idx >> 6;
                kreg[j] = packbf(K[(size_t)(2 * dp) * S + kb + k], K[(size_t)(2 * dp + 1) * S + kb + k]);
            }
#pragma unroll
            for (int j = 0; j < 8; j++) {
                int idx = j * 128 + tid;
                int d = idx >> 5, kp = idx & 31;
                float2 v2 = *(const float2*)&V[(size_t)d * S + kb + 2 * kp];
                vreg[j] = packh(v2.x, v2.y);
            }
        }

        uint32_t p[2][4][4];
        uint32_t rsh[2][2] = {{0u, 0u}, {0u, 0u}};
#pragma unroll
        for (int nn = 0; nn < 8; nn++) {
            float c[2][4];
#pragma unroll
            for (int mt = 0; mt < 2; mt++)
#pragma unroll
                for (int r = 0; r < 4; r++) c[mt][r] = 0.f;
#pragma unroll
            for (int ks = 0; ks < 2; ks++) {
                int bw = (nn * 8 + lq) * 20 + ks * 8 + lj;
                uint32_t b0 = Kbuf[bw], b1 = Kbuf[bw + 4];
                mma16816(c[0], qa[0][ks], b0, b1);
                mma16816(c[1], qa[1][ks], b0, b1);
            }
            int kk = nn >> 1, half = (nn & 1) * 2;
#pragma unroll
            for (int mt = 0; mt < 2; mt++) {
                uint32_t p01 = h2ex2(packh(c[mt][0], c[mt][1]));
                uint32_t p23 = h2ex2(packh(c[mt][2], c[mt][3]));
                rsh[mt][0] = hadd2u(rsh[mt][0], p01);
                rsh[mt][1] = hadd2u(rsh[mt][1], p23);
                p[mt][kk][half + 0] = p01;
                p[mt][kk][half + 1] = p23;
            }
        }
#pragma unroll
        for (int mt = 0; mt < 2; mt++) {
            float2 f0 = __half22float2(*(__half2*)&rsh[mt][0]);
            float2 f1 = __half22float2(*(__half2*)&rsh[mt][1]);
            float r0 = f0.x + f0.y, r1 = f1.x + f1.y;
            r0 += __shfl_xor_sync(0xffffffffu, r0, 1);
            r0 += __shfl_xor_sync(0xffffffffu, r0, 2);
            r1 += __shfl_xor_sync(0xffffffffu, r1, 1);
            r1 += __shfl_xor_sync(0xffffffffu, r1, 2);
            l_acc[mt * 2 + 0] += r0;
            l_acc[mt * 2 + 1] += r1;
        }

#pragma unroll
        for (int nt = 0; nt < 4; nt++) {
#pragma unroll
            for (int kk = 0; kk < 4; kk++) {
                int bw = (nt * 8 + lq) * 35 + kk * 8 + lj;
                uint32_t b0 = Vbuf[bw], b1 = Vbuf[bw + 4];
                mma16816h(oacc[0][nt], p[0][kk], b0, b1);
                mma16816h(oacc[1][nt], p[1][kk], b0, b1);
            }
        }
    }

    __syncthreads();
    float* Osm = (float*)smw;
    float inv[4];
#pragma unroll
    for (int r = 0; r < 4; r++) inv[r] = 1.0f / l_acc[r];
#pragma unroll
    for (int mt = 0; mt < 2; mt++) {
        int r0 = 32 * w + 16 * mt + lq;
#pragma unroll
        for (int nt = 0; nt < 4; nt++) {
            int d0 = nt * 8 + 2 * lj;
            Osm[(d0 + 0) * 130 + r0]     = oacc[mt][nt][0] * inv[mt * 2];
            Osm[(d0 + 1) * 130 + r0]     = oacc[mt][nt][1] * inv[mt * 2];
            Osm[(d0 + 0) * 130 + r0 + 8] = oacc[mt][nt][2] * inv[mt * 2 + 1];
            Osm[(d0 + 1) * 130 + r0 + 8] = oacc[mt][nt][3] * inv[mt * 2 + 1];
        }
    }
    __syncthreads();
    for (int i = tid; i < 4096; i += 128) {
        int d = i >> 7, q = i & 127;
        Out[(size_t)d * S + q0 + q] = Osm[d * 130 + q];
    }
}

// ---------------- 3x3 conv: cp.async double-buffered, pre-packed weights ----------------
// dynamic smem layout (words): patch0[0,5312) patch1[5312,10624) wfrag(2x1152 uint4) after
#define CONV_PATCH_W 5312
#define CONV_SMEM_BYTES 79360

__global__ __launch_bounds__(256)
void conv_tc_kernel(const float* __restrict__ Zin, const float* __restrict__ hin,
                    const float* __restrict__ bo, float* __restrict__ out) {
    extern __shared__ uint32_t dynsm[];
    uint32_t* patchB[2] = {dynsm, dynsm + CONV_PATCH_W};
    uint4* wfB = (uint4*)(dynsm + 2 * CONV_PATCH_W);
    uint32_t patch_a[2] = {smem_u32(patchB[0]), smem_u32(patchB[1])};
    uint32_t wf_a[2] = {smem_u32(wfB), smem_u32(wfB + 1152)};

    int tid = threadIdx.x;
    int w = tid >> 5, lane = tid & 31;
    int lq = lane >> 2, l4 = lane & 3;
    int n = blockIdx.z, cog = blockIdx.y, tile = blockIdx.x;
    int ty0 = (tile >> 2) * 16, tx0 = (tile & 3) * 16;

    int pos0 = tid;
    int yy0 = pos0 / 18 + ty0 - 1, xx0 = pos0 % 18 + tx0 - 1;
    bool va0 = (yy0 >= 0 && yy0 < HH && xx0 >= 0 && xx0 < WW);
    uint32_t sz0 = va0 ? 4u : 0u;
    int g0 = va0 ? (yy0 * WW + xx0) : 0;
    int pos1 = tid + 256;
    bool has1 = pos1 < 324;
    int yy1 = pos1 / 18 + ty0 - 1, xx1 = pos1 % 18 + tx0 - 1;
    bool va1 = has1 && (yy1 >= 0 && yy1 < HH && xx1 >= 0 && xx1 < WW);
    uint32_t sz1 = va1 ? 4u : 0u;
    int g1 = va1 ? (yy1 * WW + xx1) : 0;

    int bbase[4];
#pragma unroll
    for (int nt = 0; nt < 4; nt++)
        bbase[nt] = (2 * w + (nt >> 1)) * 18 + (nt & 1) * 8 + lq;

    const uint4* wsrc_base = g_wfrag + (size_t)cog * 6 * 1152;

    // ---- staging: issue cp.async for ci-group cig into buffer bsel
    auto stage = [&](int cig, int bsel) {
        const float* base = (cig < 2)
            ? Zin + ((size_t)n * 32 + cig * 16) * S
            : hin + ((size_t)n * 64 + (cig * 16 - 32)) * S;
        uint32_t pa = patch_a[bsel];
#pragma unroll
        for (int ci = 0; ci < 16; ci++)
            cpa4(pa + (ci * 332 + pos0) * 4, base + (size_t)ci * S + g0, sz0);
        if (has1) {
#pragma unroll
            for (int ci = 0; ci < 16; ci++)
                cpa4(pa + (ci * 332 + pos1) * 4, base + (size_t)ci * S + g1, sz1);
        }
        uint32_t wa = wf_a[bsel];
        const uint4* ws = wsrc_base + cig * 1152;
#pragma unroll
        for (int k = 0; k < 4; k++)
            cpa16(wa + (k * 256 + tid) * 16, ws + k * 256 + tid);
        if (tid < 128) cpa16(wa + (1024 + tid) * 16, ws + 1024 + tid);
        CP_COMMIT();
    };

    float oacc[2][4][4];
#pragma unroll
    for (int mt = 0; mt < 2; mt++)
#pragma unroll
        for (int nt = 0; nt < 4; nt++)
#pragma unroll
            for (int r = 0; r < 4; r++) oacc[mt][nt][r] = 0.f;

    stage(0, 0);
    CP_WAIT0();
    __syncthreads();

#pragma unroll 1
    for (int cig = 0; cig < 6; cig++) {
        int cur = cig & 1;
        if (cig < 5) stage(cig + 1, cur ^ 1);

        const uint32_t* pc = patchB[cur];
        const uint32_t* rowA = pc + l4 * 332;
        const uint32_t* rowB = pc + (8 + l4) * 332;
        const uint4* wf = wfB + cur * 1152;

#pragma unroll
        for (int khkw = 0; khkw < 9; khkw++) {
            int kh = khkw / 3, kw = khkw % 3;
#pragma unroll
            for (int c8 = 0; c8 < 2; c8++) {
                int chunk = khkw * 2 + c8;
                uint4 a0 = wf[(chunk * 2 + 0) * 32 + lane];
                uint4 a1 = wf[(chunk * 2 + 1) * 32 + lane];
                const uint32_t* rr = c8 ? rowB : rowA;
#pragma unroll
                for (int nt = 0; nt < 4; nt++) {
                    int off = bbase[nt] + kh * 18 + kw;
                    uint32_t b0 = rr[off];
                    uint32_t b1 = rr[4 * 332 + off];
                    mma1688t(oacc[0][nt], (const uint32_t*)&a0, b0, b1);
                    mma1688t(oacc[1][nt], (const uint32_t*)&a1, b0, b1);
                }
            }
        }
        CP_WAIT0();
        __syncthreads();
    }

#pragma unroll
    for (int mt = 0; mt < 2; mt++) {
        int coA = cog * 32 + mt * 16 + lq;
        int coB = coA + 8;
        float bA = bo[coA], bB = bo[coB];
        size_t baseA = ((size_t)n * 192 + coA) * S;
        size_t baseB = ((size_t)n * 192 + coB) * S;
#pragma unroll
        for (int nt = 0; nt < 4; nt++) {
            int y = ty0 + 2 * w + (nt >> 1);
            int x = tx0 + (nt & 1) * 8 + 2 * l4;
            *(float2*)&out[baseA + y * WW + x] = make_float2(oacc[mt][nt][0] + bA, oacc[mt][nt][1] + bA);
            *(float2*)&out[baseB + y * WW + x] = make_float2(oacc[mt][nt][2] + bB, oacc[mt][nt][3] + bB);
        }
    }
}

// ---------------- gates (float4) ----------------
__global__ __launch_bounds__(256)
void gates_kernel(const float* __restrict__ conv, const float* __restrict__ m,
                  float* __restrict__ out) {
    int idx4 = blockIdx.x * 256 + threadIdx.x;
    int n = idx4 >> 16;
    int rem = (idx4 & 65535) * 4;
    size_t base = (size_t)n * 192 * S;
    float4 iv = *(const float4*)&conv[base + rem];
    float4 gv = *(const float4*)&conv[base + 64 * S + rem];
    float4 ov = *(const float4*)&conv[base + 128 * S + rem];
    float4 mi = *(const float4*)&m[(size_t)n * 64 * S + rem];
    float4 hn, mn;
    {
        float si = 1.0f / (1.0f + __expf(-iv.x)), gg = tanhf(gv.x), so = 1.0f / (1.0f + __expf(-ov.x));
        mn.x = si * gg + (1.0f - si) * mi.x; hn.x = so * mn.x;
        si = 1.0f / (1.0f + __expf(-iv.y)); gg = tanhf(gv.y); so = 1.0f / (1.0f + __expf(-ov.y));
        mn.y = si * gg + (1.0f - si) * mi.y; hn.y = so * mn.y;
        si = 1.0f / (1.0f + __expf(-iv.z)); gg = tanhf(gv.z); so = 1.0f / (1.0f + __expf(-ov.z));
        mn.z = si * gg + (1.0f - si) * mi.z; hn.z = so * mn.z;
        si = 1.0f / (1.0f + __expf(-iv.w)); gg = tanhf(gv.w); so = 1.0f / (1.0f + __expf(-ov.w));
        mn.w = si * gg + (1.0f - si) * mi.w; hn.w = so * mn.w;
    }
    size_t oidx = (size_t)n * 64 * S + rem;
    *(float4*)&out[oidx] = hn;
    *(float4*)&out[1048576 + oidx] = mn;
}

// ---------------- launch ----------------
extern "C" void kernel_launch(void* const* d_in, const int* in_sizes, int n_in,
                              void* d_out, int out_size) {
    const float* h  = (const float*)d_in[0];
    const float* m  = (const float*)d_in[1];
    const float* Wh = (const float*)d_in[2];
    const float* bh = (const float*)d_in[3];
    const float* Wm = (const float*)d_in[4];
    const float* bm = (const float*)d_in[5];
    const float* Wz = (const float*)d_in[6];
    const float* bz = (const float*)d_in[7];
    const float* Wo = (const float*)d_in[8];
    const float* bo = (const float*)d_in[9];
    float* out = (float*)d_out;

    float *pHqkv, *pMkv, *pZ2, *pZp, *pConv, *pHr;
    cudaGetSymbolAddress((void**)&pHqkv, g_hqkv);
    cudaGetSymbolAddress((void**)&pMkv,  g_mkv);
    cudaGetSymbolAddress((void**)&pZ2,   g_Z2);
    cudaGetSymbolAddress((void**)&pZp,   g_Zp);
    cudaGetSymbolAddress((void**)&pConv, g_conv);
    cudaGetSymbolAddress((void**)&pHr,   g_hr);

    cudaFuncSetAttribute(conv_tc_kernel, cudaFuncAttributeMaxDynamicSharedMemorySize,
                         CONV_SMEM_BYTES);

    wpack_kernel<<<36, 256>>>(Wo);
    roundh_kernel<<<1024, 256>>>(h, pHr);
    projhm_kernel<<<dim3(32, 2, 4), 128>>>(h, Wh, bh, pHqkv, m, Wm, bm, pMkv);
    attn_mma_kernel<<<dim3(32, 2, 4), 128>>>(pHqkv, pMkv, pZ2);
    projz_kernel<<<dim3(32, 1, 4), 128>>>(pZ2, Wz, bz, pZp);
    conv_tc_kernel<<<dim3(16, 6, 4), 256, CONV_SMEM_BYTES>>>(pZp, pHr, bo, pConv);
    gates_kernel<<<1024, 256>>>(pConv, m, out);
}

// round 13
// speedup vs baseline: 1.4243x; 1.4243x over previous
#include <cuda_runtime.h>
#include <cuda_bf16.h>
#include <cuda_fp16.h>
#include <cstdint>

#define S 4096
#define HH 64
#define WW 64

// ---------------- scratch (no allocations allowed) ----------------
__device__ float g_hqkv[4 * 96 * S];
__device__ float g_mkv [4 * 64 * S];
__device__ float g_Z2  [4 * 64 * S];
__device__ float g_Zp  [4 * 32 * S];
__device__ float g_conv[4 * 192 * S];
__device__ uint32_t g_kp[4 * 2 * 65536];   // [n][att][key][dp16] bf16x2
__device__ uint32_t g_vp[4 * 2 * 65536];   // [n][att][d32][kp2048] f16x2

// ---------------- helpers ----------------
__device__ __forceinline__ uint32_t smem_u32(const void* p) {
    uint32_t a;
    asm("{ .reg .u64 t; cvta.to.shared.u64 t, %1; cvt.u32.u64 %0, t; }" : "=r"(a) : "l"(p));
    return a;
}
__device__ __forceinline__ void cpa16(uint32_t dst, const void* src) {
    asm volatile("cp.async.cg.shared.global [%0], [%1], 16;" :: "r"(dst), "l"(src));
}
#define CP_COMMIT() asm volatile("cp.async.commit_group;" ::: "memory")
#define CP_WAIT0()  asm volatile("cp.async.wait_group 0;" ::: "memory")
#define CP_WAIT1()  asm volatile("cp.async.wait_group 1;" ::: "memory")

__device__ __forceinline__ void mma16816(float* c, const uint32_t* a, uint32_t b0, uint32_t b1) {
    asm volatile(
        "mma.sync.aligned.m16n8k16.row.col.f32.bf16.bf16.f32 "
        "{%0,%1,%2,%3}, {%4,%5,%6,%7}, {%8,%9}, {%0,%1,%2,%3};"
        : "+f"(c[0]), "+f"(c[1]), "+f"(c[2]), "+f"(c[3])
        : "r"(a[0]), "r"(a[1]), "r"(a[2]), "r"(a[3]), "r"(b0), "r"(b1));
}
__device__ __forceinline__ void mma16816h(float* c, const uint32_t* a, uint32_t b0, uint32_t b1) {
    asm volatile(
        "mma.sync.aligned.m16n8k16.row.col.f32.f16.f16.f32 "
        "{%0,%1,%2,%3}, {%4,%5,%6,%7}, {%8,%9}, {%0,%1,%2,%3};"
        : "+f"(c[0]), "+f"(c[1]), "+f"(c[2]), "+f"(c[3])
        : "r"(a[0]), "r"(a[1]), "r"(a[2]), "r"(a[3]), "r"(b0), "r"(b1));
}
__device__ __forceinline__ void mma1688t(float* c, const uint32_t* a, uint32_t b0, uint32_t b1) {
    asm volatile(
        "mma.sync.aligned.m16n8k8.row.col.f32.tf32.tf32.f32 "
        "{%0,%1,%2,%3}, {%4,%5,%6,%7}, {%8,%9}, {%0,%1,%2,%3};"
        : "+f"(c[0]), "+f"(c[1]), "+f"(c[2]), "+f"(c[3])
        : "r"(a[0]), "r"(a[1]), "r"(a[2]), "r"(a[3]), "r"(b0), "r"(b1));
}
__device__ __forceinline__ uint32_t packbf(float lo, float hi) {
    uint32_t r;
    asm("cvt.rn.bf16x2.f32 %0, %2, %1;" : "=r"(r) : "f"(lo), "f"(hi));
    return r;
}
__device__ __forceinline__ uint32_t packh(float lo, float hi) {
    uint32_t r;
    asm("cvt.rn.f16x2.f32 %0, %2, %1;" : "=r"(r) : "f"(lo), "f"(hi));
    return r;
}
__device__ __forceinline__ uint32_t h2ex2(uint32_t x) {
    uint32_t r;
    asm("ex2.approx.f16x2 %0, %1;" : "=r"(r) : "r"(x));
    return r;
}
__device__ __forceinline__ uint32_t hadd2u(uint32_t a, uint32_t b) {
    uint32_t r;
    asm("add.rn.f16x2 %0, %1, %2;" : "=r"(r) : "r"(a), "r"(b));
    return r;
}
__device__ __forceinline__ uint32_t f2tf32(float f) {
    uint32_t r;
    asm("cvt.rna.tf32.f32 %0, %1;" : "=r"(r) : "f"(f));
    return r;
}

// ---------------- K/V repack: once per launch, layouts match attention smem ----------------
// Kp[key][dp] = bf16x2(K[2dp][key], K[2dp+1][key])   rows of 16 words (64B)
// Vp[d][kp]  = f16x2(V[d][2kp], V[d][2kp+1])         rows of 2048 words
__global__ __launch_bounds__(256)
void repack_kernel() {
    int n = blockIdx.z, att = blockIdx.y, bx = blockIdx.x;
    int t = threadIdx.x;
    const float* K = (att == 0) ? g_hqkv + (size_t)n * 96 * S + 32 * S
                                : g_mkv  + (size_t)n * 64 * S;
    const float* V = (att == 0) ? g_hqkv + (size_t)n * 96 * S + 64 * S
                                : g_mkv  + (size_t)n * 64 * S + 32 * S;
    uint32_t* Kp = g_kp + ((size_t)n * 2 + att) * 65536;
    uint32_t* Vp = g_vp + ((size_t)n * 2 + att) * 65536;
#pragma unroll
    for (int r = 0; r < 4; r++) {
        int j = bx * 1024 + r * 256 + t;
        int key = j & 4095, dp = j >> 12;
        Kp[key * 16 + dp] = packbf(K[(size_t)(2 * dp) * S + key],
                                   K[(size_t)(2 * dp + 1) * S + key]);
        int d = j >> 11, kp = j & 2047;
        float2 v2 = *(const float2*)&V[(size_t)d * S + 2 * kp];
        Vp[d * 2048 + kp] = packh(v2.x, v2.y);
    }
}

// ---------------- 1x1 projection as tf32 GEMM (round-10 proven) ----------------
#define PRJ_XS_ST 136
#define PRJ_WS_ST 40

__device__ __forceinline__ void proj_gemm_body(
    uint32_t* Xs, uint32_t* Ws2,
    const float* Xg, const float* Wg, const float* bg,
    float* outg, int s0)
{
    int tid = threadIdx.x;
    int w = tid >> 5, lane = tid & 31;
    int lq = lane >> 2, l4 = lane & 3;

    for (int i = tid; i < 64 * 128; i += 128) {
        int ci = i >> 7, sl = i & 127;
        Xs[ci * PRJ_XS_ST + sl] = f2tf32(Xg[(size_t)ci * S + s0 + sl]);
    }
    for (int i = tid; i < 32 * 64; i += 128) {
        int co = i >> 6, ci = i & 63;
        Ws2[ci * PRJ_WS_ST + co] = f2tf32(Wg[co * 64 + ci]);
    }
    __syncthreads();

    float oacc[2][4][4];
#pragma unroll
    for (int mt = 0; mt < 2; mt++)
#pragma unroll
        for (int nt = 0; nt < 4; nt++)
#pragma unroll
            for (int r = 0; r < 4; r++) oacc[mt][nt][r] = 0.f;

#pragma unroll
    for (int kb8 = 0; kb8 < 8; kb8++) {
        int kb = kb8 * 8;
        uint32_t a[2][4];
#pragma unroll
        for (int mt = 0; mt < 2; mt++) {
            int co0 = mt * 16 + lq;
            a[mt][0] = Ws2[(kb + l4) * PRJ_WS_ST + co0];
            a[mt][1] = Ws2[(kb + l4) * PRJ_WS_ST + co0 + 8];
            a[mt][2] = Ws2[(kb + l4 + 4) * PRJ_WS_ST + co0];
            a[mt][3] = Ws2[(kb + l4 + 4) * PRJ_WS_ST + co0 + 8];
        }
#pragma unroll
        for (int nt = 0; nt < 4; nt++) {
            int scol = w * 32 + nt * 8 + lq;
            uint32_t b0 = Xs[(kb + l4) * PRJ_XS_ST + scol];
            uint32_t b1 = Xs[(kb + l4 + 4) * PRJ_XS_ST + scol];
            mma1688t(oacc[0][nt], a[0], b0, b1);
            mma1688t(oacc[1][nt], a[1], b0, b1);
        }
    }

#pragma unroll
    for (int mt = 0; mt < 2; mt++) {
        int coA = mt * 16 + lq, coB = coA + 8;
        float bA = bg[coA], bB = bg[coB];
#pragma unroll
        for (int nt = 0; nt < 4; nt++) {
            int x = s0 + w * 32 + nt * 8 + 2 * l4;
            *(float2*)&outg[(size_t)coA * S + x] = make_float2(oacc[mt][nt][0] + bA, oacc[mt][nt][1] + bA);
            *(float2*)&outg[(size_t)coB * S + x] = make_float2(oacc[mt][nt][2] + bB, oacc[mt][nt][3] + bB);
        }
    }
}

__global__ __launch_bounds__(128)
void projhm_kernel(const float* __restrict__ h, const float* __restrict__ Wh,
                   const float* __restrict__ bh, float* __restrict__ hqkv,
                   const float* __restrict__ m, const float* __restrict__ Wm,
                   const float* __restrict__ bm, float* __restrict__ mkv) {
    __shared__ uint32_t Xs[64 * PRJ_XS_ST];
    __shared__ uint32_t Ws2[64 * PRJ_WS_ST];
    int n = blockIdx.z, y = blockIdx.y;
    int s0 = blockIdx.x * 128;
    if (y < 3) {
        int co0 = y * 32;
        proj_gemm_body(Xs, Ws2, h + (size_t)n * 64 * S, Wh + (size_t)co0 * 64, bh + co0,
                       hqkv + ((size_t)n * 96 + co0) * S, s0);
    } else {
        int co0 = (y - 3) * 32;
        proj_gemm_body(Xs, Ws2, m + (size_t)n * 64 * S, Wm + (size_t)co0 * 64, bm + co0,
                       mkv + ((size_t)n * 64 + co0) * S, s0);
    }
}

__global__ __launch_bounds__(128)
void projz_kernel(const float* __restrict__ Z2, const float* __restrict__ Wz,
                  const float* __restrict__ bz, float* __restrict__ Zp) {
    __shared__ uint32_t Xs[64 * PRJ_XS_ST];
    __shared__ uint32_t Ws2[64 * PRJ_WS_ST];
    int n = blockIdx.z;
    int s0 = blockIdx.x * 128;
    proj_gemm_body(Xs, Ws2, Z2 + (size_t)n * 64 * S, Wz, bz, Zp + (size_t)n * 32 * S, s0);
}

// ---------------- flash attention: cp.async staged from pre-packed K/V ----------------
// smem words: Qs 128x20 = 2560 | Kbuf[2] 64x20 = 1280 ea | Vbuf[2] 32x36 = 1152 ea
#define AQ_W   2560
#define AK_W   1280
#define AV_W   1152
#define A_TOT  (AQ_W + 2 * AK_W + 2 * AV_W)

__global__ __launch_bounds__(128)
void attn_mma_kernel(const float* __restrict__ hqkv, float* __restrict__ Z2) {
    __shared__ uint32_t smw[A_TOT];
    uint32_t* Qsw = smw;
    uint32_t* Kb0 = smw + AQ_W;
    uint32_t* Vb0 = smw + AQ_W + 2 * AK_W;
    __nv_bfloat16* Qh = (__nv_bfloat16*)Qsw;

    int tid = threadIdx.x;
    int w = tid >> 5, lane = tid & 31;
    int lq = lane >> 2, lj = lane & 3;
    int n = blockIdx.z, att = blockIdx.y;
    int q0 = blockIdx.x * 128;

    const float* Q = hqkv + (size_t)n * 96 * S;
    const uint32_t* Kp = g_kp + ((size_t)n * 2 + att) * 65536;
    const uint32_t* Vp = g_vp + ((size_t)n * 2 + att) * 65536;
    float* Out = Z2 + ((size_t)n * 64 + att * 32) * S;

    uint32_t kb_a[2] = {smem_u32(Kb0), smem_u32(Kb0 + AK_W)};
    uint32_t vb_a[2] = {smem_u32(Vb0), smem_u32(Vb0 + AV_W)};

    // per-thread staging coordinates (loop-invariant)
    int skey = tid >> 1, sqh = tid & 1;          // K: 2 x 16B per thread
    int svd = tid >> 2, svq = tid & 3;           // V: 2 x 16B per thread
    uint32_t kdst_off = (skey * 20 + sqh * 8) * 4;
    uint32_t vdst_off = (svd * 36 + svq * 8) * 4;

    const float scale = 0.17677669529663687f * 1.4426950408889634f;  // log2e/sqrt(32)
    for (int i = tid; i < 4096; i += 128) {
        int d = i >> 7, q = i & 127;
        Qh[q * 40 + d] = __float2bfloat16(Q[(size_t)d * S + q0 + q] * scale);
    }
    __syncthreads();

    uint32_t qa[2][2][4];
#pragma unroll
    for (int mt = 0; mt < 2; mt++) {
        int r0 = 32 * w + 16 * mt + lq;
#pragma unroll
        for (int ks = 0; ks < 2; ks++) {
            qa[mt][ks][0] = Qsw[r0 * 20 + ks * 8 + lj];
            qa[mt][ks][1] = Qsw[(r0 + 8) * 20 + ks * 8 + lj];
            qa[mt][ks][2] = Qsw[r0 * 20 + ks * 8 + lj + 4];
            qa[mt][ks][3] = Qsw[(r0 + 8) * 20 + ks * 8 + lj + 4];
        }
    }

    float oacc[2][4][4];
#pragma unroll
    for (int mt = 0; mt < 2; mt++)
#pragma unroll
        for (int nt = 0; nt < 4; nt++)
#pragma unroll
            for (int r = 0; r < 4; r++) oacc[mt][nt][r] = 0.f;
    float l_acc[4] = {0.f, 0.f, 0.f, 0.f};

    // issue stage for chunk kt into buffer bsel (4 x 16B cp.async / thread)
    auto stageA = [&](int kt, int bsel) {
        const uint32_t* ksrc = Kp + ((size_t)(kt * 64 + skey)) * 16 + sqh * 8;
        uint32_t kdst = kb_a[bsel] + kdst_off;
        cpa16(kdst, ksrc);
        cpa16(kdst + 16, ksrc + 4);
        const uint32_t* vsrc = Vp + (size_t)svd * 2048 + kt * 32 + svq * 8;
        uint32_t vdst = vb_a[bsel] + vdst_off;
        cpa16(vdst, vsrc);
        cpa16(vdst + 16, vsrc + 4);
        CP_COMMIT();
    };

    stageA(0, 0);

#pragma unroll 1
    for (int kt = 0; kt < 64; kt++) {
        if (kt < 63) {
            stageA(kt + 1, (kt + 1) & 1);
            CP_WAIT1();                     // chunk kt landed; kt+1 in flight
        } else {
            CP_WAIT0();
        }
        __syncthreads();

        const uint32_t* Kbuf = Kb0 + (kt & 1) * AK_W;
        const uint32_t* Vbuf = Vb0 + (kt & 1) * AV_W;

        // ---- QK (bf16) + base-2 softmax (f16x2 ex2) + P fragments (f16)
        uint32_t p[2][4][4];
        uint32_t rsh[2][2] = {{0u, 0u}, {0u, 0u}};
#pragma unroll
        for (int nn = 0; nn < 8; nn++) {
            float c[2][4];
#pragma unroll
            for (int mt = 0; mt < 2; mt++)
#pragma unroll
                for (int r = 0; r < 4; r++) c[mt][r] = 0.f;
#pragma unroll
            for (int ks = 0; ks < 2; ks++) {
                int bw = (nn * 8 + lq) * 20 + ks * 8 + lj;
                uint32_t b0 = Kbuf[bw], b1 = Kbuf[bw + 4];
                mma16816(c[0], qa[0][ks], b0, b1);
                mma16816(c[1], qa[1][ks], b0, b1);
            }
            int kk = nn >> 1, half = (nn & 1) * 2;
#pragma unroll
            for (int mt = 0; mt < 2; mt++) {
                uint32_t p01 = h2ex2(packh(c[mt][0], c[mt][1]));
                uint32_t p23 = h2ex2(packh(c[mt][2], c[mt][3]));
                rsh[mt][0] = hadd2u(rsh[mt][0], p01);
                rsh[mt][1] = hadd2u(rsh[mt][1], p23);
                p[mt][kk][half + 0] = p01;
                p[mt][kk][half + 1] = p23;
            }
        }
#pragma unroll
        for (int mt = 0; mt < 2; mt++) {
            float2 f0 = __half22float2(*(__half2*)&rsh[mt][0]);
            float2 f1 = __half22float2(*(__half2*)&rsh[mt][1]);
            float r0 = f0.x + f0.y, r1 = f1.x + f1.y;
            r0 += __shfl_xor_sync(0xffffffffu, r0, 1);
            r0 += __shfl_xor_sync(0xffffffffu, r0, 2);
            r1 += __shfl_xor_sync(0xffffffffu, r1, 1);
            r1 += __shfl_xor_sync(0xffffffffu, r1, 2);
            l_acc[mt * 2 + 0] += r0;
            l_acc[mt * 2 + 1] += r1;
        }

        // ---- O += P @ V (f16 MMA), V stride 36
#pragma unroll
        for (int nt = 0; nt < 4; nt++) {
#pragma unroll
            for (int kk = 0; kk < 4; kk++) {
                int bw = (nt * 8 + lq) * 36 + kk * 8 + lj;
                uint32_t b0 = Vbuf[bw], b1 = Vbuf[bw + 4];
                mma16816h(oacc[0][nt], p[0][kk], b0, b1);
                mma16816h(oacc[1][nt], p[1][kk], b0, b1);
            }
        }
        __syncthreads();   // compute done before this buffer is re-staged
    }

    // ---- epilogue: normalize, stage Osm[d][q] stride 130, coalesced store
    float* Osm = (float*)smw;
    float inv[4];
#pragma unroll
    for (int r = 0; r < 4; r++) inv[r] = 1.0f / l_acc[r];
#pragma unroll
    for (int mt = 0; mt < 2; mt++) {
        int r0 = 32 * w + 16 * mt + lq;
#pragma unroll
        for (int nt = 0; nt < 4; nt++) {
            int d0 = nt * 8 + 2 * lj;
            Osm[(d0 + 0) * 130 + r0]     = oacc[mt][nt][0] * inv[mt * 2];
            Osm[(d0 + 1) * 130 + r0]     = oacc[mt][nt][1] * inv[mt * 2];
            Osm[(d0 + 0) * 130 + r0 + 8] = oacc[mt][nt][2] * inv[mt * 2 + 1];
            Osm[(d0 + 1) * 130 + r0 + 8] = oacc[mt][nt][3] * inv[mt * 2 + 1];
        }
    }
    __syncthreads();
    for (int i = tid; i < 4096; i += 128) {
        int d = i >> 7, q = i & 127;
        Out[(size_t)d * S + q0 + q] = Osm[d * 130 + q];
    }
}

// ---------------- 3x3 conv implicit GEMM (round-10 proven, unchanged) ----------------
__global__ __launch_bounds__(256)
void conv_tc_kernel(const float* __restrict__ Zin, const float* __restrict__ hin,
                    const float* __restrict__ Wo, const float* __restrict__ bo,
                    float* __restrict__ out) {
    __shared__ uint32_t patchF[16 * 332];
    __shared__ uint4 Wfrag[18 * 2 * 32];

    int tid = threadIdx.x;
    int w = tid >> 5, lane = tid & 31;
    int lq = lane >> 2, l4 = lane & 3;
    int n = blockIdx.z, cog = blockIdx.y, tile = blockIdx.x;
    int ty0 = (tile >> 2) * 16, tx0 = (tile & 3) * 16;

    int pos0 = tid;
    int yy0 = pos0 / 18 + ty0 - 1, xx0 = pos0 % 18 + tx0 - 1;
    bool va0 = (yy0 >= 0 && yy0 < HH && xx0 >= 0 && xx0 < WW);
    int g0 = yy0 * WW + xx0;
    int pos1 = tid + 256;
    bool has1 = pos1 < 324;
    int yy1 = pos1 / 18 + ty0 - 1, xx1 = pos1 % 18 + tx0 - 1;
    bool va1 = has1 && (yy1 >= 0 && yy1 < HH && xx1 >= 0 && xx1 < WW);
    int g1 = yy1 * WW + xx1;

    const uint32_t* rowA = patchF + l4 * 332;
    const uint32_t* rowB = patchF + (8 + l4) * 332;
    int bbase[4];
#pragma unroll
    for (int nt = 0; nt < 4; nt++)
        bbase[nt] = (2 * w + (nt >> 1)) * 18 + (nt & 1) * 8 + lq;

    float oacc[2][4][4];
#pragma unroll
    for (int mt = 0; mt < 2; mt++)
#pragma unroll
        for (int nt = 0; nt < 4; nt++)
#pragma unroll
            for (int r = 0; r < 4; r++) oacc[mt][nt][r] = 0.f;

#pragma unroll 1
    for (int cig = 0; cig < 6; cig++) {
        const float* base = (cig < 2)
            ? Zin + ((size_t)n * 32 + cig * 16) * S
            : hin + ((size_t)n * 64 + (cig * 16 - 32)) * S;
        __syncthreads();
#pragma unroll
        for (int ci = 0; ci < 16; ci++)
            patchF[ci * 332 + pos0] = va0 ? f2tf32(base[(size_t)ci * S + g0]) : 0u;
        if (has1) {
#pragma unroll
            for (int ci = 0; ci < 16; ci++)
                patchF[ci * 332 + pos1] = va1 ? f2tf32(base[(size_t)ci * S + g1]) : 0u;
        }
        for (int i = tid; i < 1152; i += 256) {
            int ln = i & 31, mtc = i >> 5;
            int mt = mtc & 1, chunk = mtc >> 1;
            int khkw = chunk >> 1, c8 = chunk & 1;
            int ciL = c8 * 8 + (ln & 3);
            int co0 = mt * 16 + (ln >> 2);
            const float* wp = Wo + (((size_t)cog * 32 + co0) * 96 + cig * 16 + ciL) * 9 + khkw;
            Wfrag[i] = make_uint4(f2tf32(wp[0]), f2tf32(wp[8 * 864]),
                                  f2tf32(wp[36]), f2tf32(wp[8 * 864 + 36]));
        }
        __syncthreads();

#pragma unroll
        for (int khkw = 0; khkw < 9; khkw++) {
            int kh = khkw / 3, kw = khkw % 3;
#pragma unroll
            for (int c8 = 0; c8 < 2; c8++) {
                int chunk = khkw * 2 + c8;
                uint4 a0 = Wfrag[(chunk * 2 + 0) * 32 + lane];
                uint4 a1 = Wfrag[(chunk * 2 + 1) * 32 + lane];
                const uint32_t* rr = c8 ? rowB : rowA;
#pragma unroll
                for (int nt = 0; nt < 4; nt++) {
                    int off = bbase[nt] + kh * 18 + kw;
                    uint32_t b0 = rr[off];
                    uint32_t b1 = rr[4 * 332 + off];
                    mma1688t(oacc[0][nt], (const uint32_t*)&a0, b0, b1);
                    mma1688t(oacc[1][nt], (const uint32_t*)&a1, b0, b1);
                }
            }
        }
    }

#pragma unroll
    for (int mt = 0; mt < 2; mt++) {
        int coA = cog * 32 + mt * 16 + lq;
        int coB = coA + 8;
        float bA = bo[coA], bB = bo[coB];
        size_t baseA = ((size_t)n * 192 + coA) * S;
        size_t baseB = ((size_t)n * 192 + coB) * S;
#pragma unroll
        for (int nt = 0; nt < 4; nt++) {
            int y = ty0 + 2 * w + (nt >> 1);
            int x = tx0 + (nt & 1) * 8 + 2 * l4;
            *(float2*)&out[baseA + y * WW + x] = make_float2(oacc[mt][nt][0] + bA, oacc[mt][nt][1] + bA);
            *(float2*)&out[baseB + y * WW + x] = make_float2(oacc[mt][nt][2] + bB, oacc[mt][nt][3] + bB);
        }
    }
}

// ---------------- gates (float4) ----------------
__global__ __launch_bounds__(256)
void gates_kernel(const float* __restrict__ conv, const float* __restrict__ m,
                  float* __restrict__ out) {
    int idx4 = blockIdx.x * 256 + threadIdx.x;
    int n = idx4 >> 16;
    int rem = (idx4 & 65535) * 4;
    size_t base = (size_t)n * 192 * S;
    float4 iv = *(const float4*)&conv[base + rem];
    float4 gv = *(const float4*)&conv[base + 64 * S + rem];
    float4 ov = *(const float4*)&conv[base + 128 * S + rem];
    float4 mi = *(const float4*)&m[(size_t)n * 64 * S + rem];
    float4 hn, mn;
    {
        float si = 1.0f / (1.0f + __expf(-iv.x)), gg = tanhf(gv.x), so = 1.0f / (1.0f + __expf(-ov.x));
        mn.x = si * gg + (1.0f - si) * mi.x; hn.x = so * mn.x;
        si = 1.0f / (1.0f + __expf(-iv.y)); gg = tanhf(gv.y); so = 1.0f / (1.0f + __expf(-ov.y));
        mn.y = si * gg + (1.0f - si) * mi.y; hn.y = so * mn.y;
        si = 1.0f / (1.0f + __expf(-iv.z)); gg = tanhf(gv.z); so = 1.0f / (1.0f + __expf(-ov.z));
        mn.z = si * gg + (1.0f - si) * mi.z; hn.z = so * mn.z;
        si = 1.0f / (1.0f + __expf(-iv.w)); gg = tanhf(gv.w); so = 1.0f / (1.0f + __expf(-ov.w));
        mn.w = si * gg + (1.0f - si) * mi.w; hn.w = so * mn.w;
    }
    size_t oidx = (size_t)n * 64 * S + rem;
    *(float4*)&out[oidx] = hn;
    *(float4*)&out[1048576 + oidx] = mn;
}

// ---------------- launch ----------------
extern "C" void kernel_launch(void* const* d_in, const int* in_sizes, int n_in,
                              void* d_out, int out_size) {
    const float* h  = (const float*)d_in[0];
    const float* m  = (const float*)d_in[1];
    const float* Wh = (const float*)d_in[2];
    const float* bh = (const float*)d_in[3];
    const float* Wm = (const float*)d_in[4];
    const float* bm = (const float*)d_in[5];
    const float* Wz = (const float*)d_in[6];
    const float* bz = (const float*)d_in[7];
    const float* Wo = (const float*)d_in[8];
    const float* bo = (const float*)d_in[9];
    float* out = (float*)d_out;

    float *pHqkv, *pMkv, *pZ2, *pZp, *pConv;
    cudaGetSymbolAddress((void**)&pHqkv, g_hqkv);
    cudaGetSymbolAddress((void**)&pMkv,  g_mkv);
    cudaGetSymbolAddress((void**)&pZ2,   g_Z2);
    cudaGetSymbolAddress((void**)&pZp,   g_Zp);
    cudaGetSymbolAddress((void**)&pConv, g_conv);

    projhm_kernel<<<dim3(32, 5, 4), 128>>>(h, Wh, bh, pHqkv, m, Wm, bm, pMkv);
    repack_kernel<<<dim3(64, 2, 4), 256>>>();
    attn_mma_kernel<<<dim3(32, 2, 4), 128>>>(pHqkv, pZ2);
    projz_kernel<<<dim3(32, 1, 4), 128>>>(pZ2, Wz, bz, pZp);
    conv_tc_kernel<<<dim3(16, 6, 4), 256>>>(pZp, h, Wo, bo, pConv);
    gates_kernel<<<1024, 256>>>(pConv, m, out);
}